// round 16
// baseline (speedup 1.0000x reference)
#include <cuda_runtime.h>
#include <cuda_bf16.h>
#include <math.h>
#include <float.h>
#include <stdint.h>

#define BB 8
#define NQ 4096
#define QD 1280
#define CD 1024
#define CTX 85
#define NHEADS 20
#define DHEAD 64
#define INNER (NHEADS*DHEAD)   // 1280
#define KVN (2*INNER)          // 2560
#define MKV 768
#define NBH (BB*NHEADS)        // 160
#define MHALF (BB*NQ/2)        // 16384 rows per batch-half

typedef unsigned short ushort_t;

// ---------------- scratch (static device globals; no allocation) -------------
__device__ float g_kv[(size_t)MKV*KVN];
__device__ __nv_bfloat16 g_qhi[(size_t)BB*NQ*INNER];
__device__ __nv_bfloat16 g_qlo[(size_t)BB*NQ*INNER];
__device__ __nv_bfloat16 g_ao_hi[(size_t)BB*NQ*INNER];
__device__ __nv_bfloat16 g_ao_lo[(size_t)BB*NQ*INNER];
__device__ __nv_bfloat16 g_wqt_hi[(size_t)INNER*QD];
__device__ __nv_bfloat16 g_wqt_lo[(size_t)INNER*QD];
__device__ __nv_bfloat16 g_wkvt_hi[(size_t)KVN*CD];
__device__ __nv_bfloat16 g_wkvt_lo[(size_t)KVN*CD];
__device__ __nv_bfloat16 g_wot_hi[(size_t)QD*INNER];
__device__ __nv_bfloat16 g_wot_lo[(size_t)QD*INNER];
__device__ __nv_bfloat16 g_kimg_hi[(size_t)NBH*96*64];
__device__ __nv_bfloat16 g_kimg_lo[(size_t)NBH*96*64];
__device__ __nv_bfloat16 g_vimg_hi[(size_t)NBH*64*128];
__device__ __nv_bfloat16 g_vimg_lo[(size_t)NBH*64*128];
__device__ unsigned char g_fg[BB*NQ];

// ============================ PTX helpers ====================================
__device__ __forceinline__ uint32_t smem_to_u32(const void* p) {
    uint32_t a;
    asm("{ .reg .u64 t; cvta.to.shared.u64 t, %1; cvt.u32.u64 %0, t; }"
        : "=r"(a) : "l"(p));
    return a;
}

#if defined(__CUDA_ARCH_FEAT_SM103_ALL)
#define HAS_TCGEN05 1
#else
#define HAS_TCGEN05 0
#endif

#if HAS_TCGEN05
__device__ __forceinline__ uint32_t elect_one_pred() {
    uint32_t pred;
    asm volatile(
        "{\n\t.reg .pred p;\n\t"
        "elect.sync _|p, 0xFFFFFFFF;\n\t"
        "selp.b32 %0, 1, 0, p;\n\t}"
        : "=r"(pred));
    return pred;
}
#define TCGEN05_ALLOC(sa, n) \
    asm volatile("tcgen05.alloc.cta_group::1.sync.aligned.shared::cta.b32 [%0], %1;" \
        :: "r"((uint32_t)(sa)), "r"((uint32_t)(n)) : "memory")
#define TCGEN05_DEALLOC(t, n) \
    asm volatile("tcgen05.dealloc.cta_group::1.sync.aligned.b32 %0, %1;" :: "r"(t), "r"((uint32_t)(n)))
#define TCGEN05_RELINQ() \
    asm volatile("tcgen05.relinquish_alloc_permit.cta_group::1.sync.aligned;")
#define TCGEN05_COMMIT(mb) \
    asm volatile("tcgen05.commit.cta_group::1.mbarrier::arrive::one.shared::cluster.b64 [%0];" \
        :: "r"((uint32_t)(mb)) : "memory")
#define TCGEN05_FENCE_AFTER() asm volatile("tcgen05.fence::after_thread_sync;" ::: "memory")
#define TCGEN05_FENCE_BEFORE() asm volatile("tcgen05.fence::before_thread_sync;" ::: "memory")
#define TCGEN05_WAIT_LD() asm volatile("tcgen05.wait::ld.sync.aligned;" ::: "memory")
#define FENCE_ASYNC() asm volatile("fence.proxy.async.shared::cta;" ::: "memory")
#define MBARRIER_INIT(mb, c) \
    asm volatile("mbarrier.init.shared.b64 [%0], %1;" :: "r"((uint32_t)(mb)), "r"((uint32_t)(c)) : "memory")
#define MBARRIER_WAIT_PARITY(mb, ph) do { \
    uint32_t _m = (uint32_t)(mb), _p = (uint32_t)(ph), _d; \
    asm volatile("{\n\t.reg .pred p;\n\t" \
        "mbarrier.try_wait.parity.acquire.cta.shared::cta.b64 p, [%1], %2;\n\t" \
        "selp.b32 %0, 1, 0, p;\n\t}" : "=r"(_d) : "r"(_m), "r"(_p) : "memory"); \
    if (!_d) { \
        asm volatile("{\n\t.reg .pred P1;\n\t" \
            "WL_%=:\n\t" \
            "mbarrier.try_wait.parity.acquire.cta.shared::cta.b64 P1, [%0], %1, 0x989680;\n\t" \
            "@P1 bra.uni WD_%=;\n\t" \
            "bra.uni WL_%=;\n\t" \
            "WD_%=:\n\t}" :: "r"(_m), "r"(_p) : "memory"); \
    } \
} while (0)
#define TCGEN05_LD_32X32B_X32(r, ta) \
    asm volatile("tcgen05.ld.sync.aligned.32x32b.x32.b32 " \
        "{%0, %1, %2, %3, %4, %5, %6, %7, %8, %9, %10, %11, %12, %13, %14, %15, " \
        " %16, %17, %18, %19, %20, %21, %22, %23, %24, %25, %26, %27, %28, %29, %30, %31}, [%32];" \
        : "=r"((r)[0]),  "=r"((r)[1]),  "=r"((r)[2]),  "=r"((r)[3]), \
          "=r"((r)[4]),  "=r"((r)[5]),  "=r"((r)[6]),  "=r"((r)[7]), \
          "=r"((r)[8]),  "=r"((r)[9]),  "=r"((r)[10]), "=r"((r)[11]), \
          "=r"((r)[12]), "=r"((r)[13]), "=r"((r)[14]), "=r"((r)[15]), \
          "=r"((r)[16]), "=r"((r)[17]), "=r"((r)[18]), "=r"((r)[19]), \
          "=r"((r)[20]), "=r"((r)[21]), "=r"((r)[22]), "=r"((r)[23]), \
          "=r"((r)[24]), "=r"((r)[25]), "=r"((r)[26]), "=r"((r)[27]), \
          "=r"((r)[28]), "=r"((r)[29]), "=r"((r)[30]), "=r"((r)[31]) \
        : "r"(ta))

__device__ __forceinline__ void mma_f16_ss(uint32_t d_tmem, uint64_t a_desc,
                                           uint64_t b_desc, uint32_t idesc, bool acc)
{
    uint32_t en = acc ? 1u : 0u;
    asm volatile(
        "{\n\t.reg .pred p;\n\t"
        "setp.ne.u32 p, %5, 0;\n\t"
        "tcgen05.mma.cta_group::1.kind::f16 [%0], %1, %2, %3, {%4, %4, %4, %4}, p;\n\t}"
        :: "r"(d_tmem), "l"(a_desc), "l"(b_desc), "r"(idesc), "r"(0u), "r"(en)
        : "memory");
}
#endif // HAS_TCGEN05

static constexpr uint64_t SMEM_DESC_BASE_SW128 =
    (uint64_t(2)  << 61) | (uint64_t(1) << 46) | (uint64_t(64) << 32) | (uint64_t(1) << 16);
#define MAKE_SMEM_DESC(ba) (SMEM_DESC_BASE_SW128 | ((uint64_t)((ba) >> 4) & 0x3FFF))
#define SMEM_SWIZZLE_128B(bo) ((bo) ^ (((bo) >> 3) & 0x70))

__device__ __forceinline__ void bf16split(float f, ushort_t& h, ushort_t& l)
{
    __nv_bfloat16 hh = __float2bfloat16(f);
    __nv_bfloat16 ll = __float2bfloat16(f - __bfloat162float(hh));
    h = __bfloat16_as_ushort(hh);
    l = __bfloat16_as_ushort(ll);
}

// ---------------- mask: exact integer bicubic-threshold ----------------------
__global__ void mask_kernel(const int* __restrict__ mask)
{
    int idx = blockIdx.x * blockDim.x + threadIdx.x;
    if (idx >= BB*NQ) return;
    int b = idx / NQ, n = idx % NQ;
    int o = n >> 6, p = n & 63;
    const int iw[4] = {-3, 19, 19, -3};
    const int* mb = mask + (size_t)b * 256 * 256;
    int acc = 0;
#pragma unroll
    for (int s = 0; s < 4; s++) {
        const int* row = mb + (4*o + s) * 256 + 4*p;
        int rw = iw[s];
#pragma unroll
        for (int t = 0; t < 4; t++) acc += rw * iw[t] * row[t];
    }
    g_fg[idx] = (acc != 0) ? 1 : 0;
}

// ---------------- weight transpose + bf16 split -------------------------------
__global__ void wtrans_kernel(const float* __restrict__ W,
                              __nv_bfloat16* __restrict__ Thi,
                              __nv_bfloat16* __restrict__ Tlo, int K, int N)
{
    __shared__ float t[32][33];
    int k0 = blockIdx.x * 32, n0 = blockIdx.y * 32;
    int tx = threadIdx.x, ty = threadIdx.y;
    for (int r = ty; r < 32; r += 8)
        t[r][tx] = W[(size_t)(k0 + r)*N + n0 + tx];
    __syncthreads();
    for (int r = ty; r < 32; r += 8) {
        float v = t[tx][r];
        ushort_t h, l; bf16split(v, h, l);
        Thi[(size_t)(n0 + r)*K + k0 + tx] = __ushort_as_bfloat16(h);
        Tlo[(size_t)(n0 + r)*K + k0 + tx] = __ushort_as_bfloat16(l);
    }
}

// ================= bf16x3 tcgen05 GEMM: C = A@B^T (+bias) ====================
#define G_BM 128
#define G_BN 256
#define G_BK 64
#define G_BUFSZ 98304
#define G_SMEM  (2048 + 2*G_BUFSZ)
#define G_IDESC 0x08400490u   // F32 acc, BF16xBF16, N=256, M=128

__global__ void __launch_bounds__(256)
gemm_bf16x3(const float* __restrict__ Af,
            const __nv_bfloat16* __restrict__ Ahi, const __nv_bfloat16* __restrict__ Alo,
            const __nv_bfloat16* __restrict__ Bhi, const __nv_bfloat16* __restrict__ Blo,
            const float* __restrict__ bias, float* __restrict__ C,
            __nv_bfloat16* __restrict__ Chi, __nv_bfloat16* __restrict__ Clo,
            int Mvalid, int N, int K)
{
#if HAS_TCGEN05
    extern __shared__ char smem[];
    const uint32_t sb = smem_to_u32(smem);
    const uint32_t ab = (sb + 1024 + 1023) & ~1023u;
    char* abp = smem + (ab - sb);
    const int tid = threadIdx.x;
    const int wid = tid >> 5, lane = tid & 31;
    const int brow = blockIdx.y * G_BM;
    const int bcol = blockIdx.x * G_BN;

    if (wid == 0) TCGEN05_ALLOC(sb, 256);
    __syncthreads();
    uint32_t tmem;
    asm volatile("ld.shared.b32 %0, [%1];" : "=r"(tmem) : "r"(sb));
    if (wid == 0) TCGEN05_RELINQ();
    if (tid == 0) { MBARRIER_INIT(sb + 8, 1); MBARRIER_INIT(sb + 16, 1); }
    __syncthreads();

    const int KCH = K / G_BK;
    int par0 = 0, par1 = 0;

    uint4 pa0[4], pa1[4], pbh[8], pbl[8];
    const int a_row = tid >> 3;
    const int a_v   = tid & 7;

    auto load_chunk = [&](int c) {
        const int k0 = c * G_BK;
        if (Af) {
#pragma unroll
            for (int i = 0; i < 4; ++i) {
                int gr = brow + a_row + i*32;
                if (gr < Mvalid) {
                    const uint4* src = (const uint4*)(Af + (size_t)gr*K + k0 + a_v*8);
                    pa0[i] = src[0];
                    pa1[i] = src[1];
                } else {
                    pa0[i] = make_uint4(0u,0u,0u,0u);
                    pa1[i] = make_uint4(0u,0u,0u,0u);
                }
            }
        } else {
#pragma unroll
            for (int i = 0; i < 4; ++i) {
                int gr = brow + a_row + i*32;
                pa0[i] = *(const uint4*)(Ahi + (size_t)gr*K + k0 + a_v*8);
                pa1[i] = *(const uint4*)(Alo + (size_t)gr*K + k0 + a_v*8);
            }
        }
#pragma unroll
        for (int i = 0; i < 8; ++i) {
            int row = a_row + i*32;
            pbh[i] = *(const uint4*)(Bhi + (size_t)(bcol + row)*K + k0 + a_v*8);
            pbl[i] = *(const uint4*)(Blo + (size_t)(bcol + row)*K + k0 + a_v*8);
        }
    };

    load_chunk(0);

    for (int c = 0; c < KCH; ++c) {
        int p = c & 1;
        if (c >= 2) {
            if (p == 0) { MBARRIER_WAIT_PARITY(sb + 8, par0); par0 ^= 1; }
            else        { MBARRIER_WAIT_PARITY(sb + 16, par1); par1 ^= 1; }
        }
        char* base = abp + p * G_BUFSZ;

#pragma unroll
        for (int i = 0; i < 4; ++i) {
            uint32_t so = SMEM_SWIZZLE_128B((uint32_t)((a_row + i*32)*128 + a_v*16));
            uint4 vh, vl;
            if (Af) {
                const float* f0 = (const float*)&pa0[i];
                const float* f1 = (const float*)&pa1[i];
                float fa[8] = {f0[0], f0[1], f0[2], f0[3], f1[0], f1[1], f1[2], f1[3]};
                uint32_t hw[4], lw[4];
#pragma unroll
                for (int e = 0; e < 4; ++e) {
                    ushort_t h0, l0, h1, l1;
                    bf16split(fa[2*e],   h0, l0);
                    bf16split(fa[2*e+1], h1, l1);
                    hw[e] = ((uint32_t)h1 << 16) | h0;
                    lw[e] = ((uint32_t)l1 << 16) | l0;
                }
                vh = make_uint4(hw[0], hw[1], hw[2], hw[3]);
                vl = make_uint4(lw[0], lw[1], lw[2], lw[3]);
            } else {
                vh = pa0[i];
                vl = pa1[i];
            }
            *(uint4*)(base + so) = vh;
            *(uint4*)(base + 16384 + so) = vl;
        }
#pragma unroll
        for (int i = 0; i < 8; ++i) {
            uint32_t so = SMEM_SWIZZLE_128B((uint32_t)((a_row + i*32)*128 + a_v*16));
            *(uint4*)(base + 32768 + so) = pbh[i];
            *(uint4*)(base + 65536 + so) = pbl[i];
        }
        __syncthreads();

        if (wid == 0 && elect_one_pred()) {
            FENCE_ASYNC();
            uint32_t bu = ab + p * G_BUFSZ;
            uint64_t dah = MAKE_SMEM_DESC(bu);
            uint64_t dal = MAKE_SMEM_DESC(bu + 16384);
            uint64_t dbh = MAKE_SMEM_DESC(bu + 32768);
            uint64_t dbl = MAKE_SMEM_DESC(bu + 65536);
#pragma unroll
            for (int ks = 0; ks < 4; ++ks)
                mma_f16_ss(tmem, dah + ks*2, dbh + ks*2, G_IDESC, !(c == 0 && ks == 0));
#pragma unroll
            for (int ks = 0; ks < 4; ++ks)
                mma_f16_ss(tmem, dah + ks*2, dbl + ks*2, G_IDESC, true);
#pragma unroll
            for (int ks = 0; ks < 4; ++ks)
                mma_f16_ss(tmem, dal + ks*2, dbh + ks*2, G_IDESC, true);
            TCGEN05_COMMIT(sb + 8 + p*8);
        }

        if (c + 1 < KCH) load_chunk(c + 1);
    }
    MBARRIER_WAIT_PARITY(sb + 8, par0);
    MBARRIER_WAIT_PARITY(sb + 16, par1);
    TCGEN05_FENCE_AFTER();

    if (wid < 4) {
        int row = brow + wid*32 + lane;
#pragma unroll
        for (int cb = 0; cb < G_BN/32; ++cb) {
            uint32_t r[32];
            TCGEN05_LD_32X32B_X32(r, tmem + cb*32);
            TCGEN05_WAIT_LD();
            int col0 = bcol + cb*32;
            if (Chi) {
                uint32_t hp[16], lp[16];
#pragma unroll
                for (int m = 0; m < 16; ++m) {
                    ushort_t h0, l0, h1, l1;
                    bf16split(__uint_as_float(r[2*m]),   h0, l0);
                    bf16split(__uint_as_float(r[2*m+1]), h1, l1);
                    hp[m] = ((uint32_t)h1 << 16) | h0;
                    lp[m] = ((uint32_t)l1 << 16) | l0;
                }
                uint32_t* dh = (uint32_t*)(Chi + (size_t)row*N + col0);
                uint32_t* dl = (uint32_t*)(Clo + (size_t)row*N + col0);
#pragma unroll
                for (int m = 0; m < 16; ++m) { dh[m] = hp[m]; dl[m] = lp[m]; }
            } else {
                float* cp = C + (size_t)row*N + col0;
                if (bias) {
#pragma unroll
                    for (int i = 0; i < 32; ++i) cp[i] = __uint_as_float(r[i]) + bias[col0 + i];
                } else {
#pragma unroll
                    for (int i = 0; i < 32; ++i) cp[i] = __uint_as_float(r[i]);
                }
            }
        }
        TCGEN05_FENCE_BEFORE();
    }
    __syncthreads();
    if (wid == 0) TCGEN05_DEALLOC(tmem, 256);
#endif
}

// ---------------- K / V^T image bake (from merged g_kv) -----------------------
__global__ void __launch_bounds__(128) kv_image_kernel()
{
    int bh = blockIdx.x;
    int b = bh / NHEADS, h = bh % NHEADS;
    int tid = threadIdx.x;
    char* kh = (char*)(g_kimg_hi + (size_t)bh*96*64);
    char* kl = (char*)(g_kimg_lo + (size_t)bh*96*64);
    char* vh = (char*)(g_vimg_hi + (size_t)bh*64*128);
    char* vl = (char*)(g_vimg_lo + (size_t)bh*64*128);

    for (int u = tid; u < 96*64; u += 128) {
        int j = u >> 6, d = u & 63;
        float f = (j < CTX) ? g_kv[(size_t)(b*CTX + j)*KVN + h*DHEAD + d] : 0.f;
        ushort_t hh, ll; bf16split(f, hh, ll);
        uint32_t so = SMEM_SWIZZLE_128B((uint32_t)(j*128 + d*2));
        *(ushort_t*)(kh + so) = hh;
        *(ushort_t*)(kl + so) = ll;
    }
    for (int u = tid; u < 64*128; u += 128) {
        int d = u >> 7, j = u & 127;
        float f = (j < CTX) ? g_kv[(size_t)(b*CTX + j)*KVN + INNER + h*DHEAD + d] : 0.f;
        ushort_t hh, ll; bf16split(f, hh, ll);
        uint32_t addr = (uint32_t)(((d >> 3) + (j >> 6)*8)*1024 + (d & 7)*128 + (j & 63)*2);
        uint32_t so = SMEM_SWIZZLE_128B(addr);
        *(ushort_t*)(vh + so) = hh;
        *(ushort_t*)(vl + so) = ll;
    }
}

// ---------------- tcgen05 fused masked attention (pipelined, batch-split) -----
#define ATT_QT 8
#define A_KHI 0
#define A_KLO 12288
#define A_VHI 24576
#define A_VLO 40960
#define A_Q0  57344
#define A_PHI 122880
#define A_PLO 155648
#define ATTN_SMEM (2048 + 188416)
#define IDESC_S 0x08180490u
#define IDESC_O 0x08100490u

#if HAS_TCGEN05
__device__ __forceinline__ void attn_issue_S(uint32_t tmem, uint32_t ab, int t)
{
    uint32_t qb = ab + A_Q0 + (uint32_t)(t & 1)*32768;
    uint64_t dqh = MAKE_SMEM_DESC(qb);
    uint64_t dql = MAKE_SMEM_DESC(qb + 16384);
    uint64_t dkh = MAKE_SMEM_DESC(ab + A_KHI);
    uint64_t dkl = MAKE_SMEM_DESC(ab + A_KLO);
    uint32_t dst = tmem + (uint32_t)(t & 1)*96;
#pragma unroll
    for (int ks = 0; ks < 4; ++ks)
        mma_f16_ss(dst, dqh + ks*2, dkh + ks*2, IDESC_S, ks > 0);
#pragma unroll
    for (int ks = 0; ks < 4; ++ks)
        mma_f16_ss(dst, dqh + ks*2, dkl + ks*2, IDESC_S, true);
#pragma unroll
    for (int ks = 0; ks < 4; ++ks)
        mma_f16_ss(dst, dql + ks*2, dkh + ks*2, IDESC_S, true);
}

__device__ __forceinline__ void attn_issue_O(uint32_t tmem, uint32_t ab, int t)
{
    uint64_t dph = MAKE_SMEM_DESC(ab + A_PHI);
    uint64_t dpl = MAKE_SMEM_DESC(ab + A_PLO);
    uint64_t dvh = MAKE_SMEM_DESC(ab + A_VHI);
    uint64_t dvl = MAKE_SMEM_DESC(ab + A_VLO);
    uint32_t dst = tmem + 192 + (uint32_t)(t & 1)*64;
#pragma unroll
    for (int ks = 0; ks < 8; ++ks) {
        uint64_t aoff = (ks < 4) ? ks*2 : 1024 + (ks-4)*2;
        uint64_t boff = (ks < 4) ? ks*2 : 512 + (ks-4)*2;
        mma_f16_ss(dst, dph + aoff, dvh + boff, IDESC_O, ks > 0);
    }
#pragma unroll
    for (int ks = 0; ks < 8; ++ks) {
        uint64_t aoff = (ks < 4) ? ks*2 : 1024 + (ks-4)*2;
        uint64_t boff = (ks < 4) ? ks*2 : 512 + (ks-4)*2;
        mma_f16_ss(dst, dph + aoff, dvl + boff, IDESC_O, true);
    }
#pragma unroll
    for (int ks = 0; ks < 8; ++ks) {
        uint64_t aoff = (ks < 4) ? ks*2 : 1024 + (ks-4)*2;
        uint64_t boff = (ks < 4) ? ks*2 : 512 + (ks-4)*2;
        mma_f16_ss(dst, dpl + aoff, dvh + boff, IDESC_O, true);
    }
}
#endif

__global__ void __launch_bounds__(128) attn_tc(int b_off)
{
#if HAS_TCGEN05
    extern __shared__ char smem[];
    const uint32_t sb = smem_to_u32(smem);
    const uint32_t ab = (sb + 1024 + 1023) & ~1023u;
    char* abp = smem + (ab - sb);
    int tid = threadIdx.x, wid = tid >> 5;
    int b = blockIdx.z + b_off, h = blockIdx.y, qg = blockIdx.x;
    int bh = b*NHEADS + h;

    if (wid == 0) TCGEN05_ALLOC(sb, 512);
    __syncthreads();
    uint32_t tmem;
    asm volatile("ld.shared.b32 %0, [%1];" : "=r"(tmem) : "r"(sb));
    if (wid == 0) TCGEN05_RELINQ();
    if (tid == 0) { MBARRIER_INIT(sb + 8, 1); MBARRIER_INIT(sb + 16, 1); }
    __syncthreads();

    {
        const uint4* skh = (const uint4*)(g_kimg_hi + (size_t)bh*96*64);
        const uint4* skl = (const uint4*)(g_kimg_lo + (size_t)bh*96*64);
        for (int u = tid; u < 768; u += 128) {
            ((uint4*)(abp + A_KHI))[u] = skh[u];
            ((uint4*)(abp + A_KLO))[u] = skl[u];
        }
        const uint4* svh = (const uint4*)(g_vimg_hi + (size_t)bh*64*128);
        const uint4* svl = (const uint4*)(g_vimg_lo + (size_t)bh*64*128);
        for (int u = tid; u < 1024; u += 128) {
            ((uint4*)(abp + A_VHI))[u] = svh[u];
            ((uint4*)(abp + A_VLO))[u] = svl[u];
        }
    }
    {
        int qbase = qg*ATT_QT*128;
        size_t qrow = (size_t)(b*NQ + qbase + tid)*INNER + h*DHEAD;
        const uint4* qh = (const uint4*)(g_qhi + qrow);
        const uint4* ql = (const uint4*)(g_qlo + qrow);
#pragma unroll
        for (int v = 0; v < 8; ++v) {
            uint32_t so = SMEM_SWIZZLE_128B((uint32_t)(tid*128 + v*16));
            *(uint4*)(abp + A_Q0 + so) = qh[v];
            *(uint4*)(abp + A_Q0 + 16384 + so) = ql[v];
        }
    }
    __syncthreads();
    if (wid == 0 && elect_one_pred()) {
        FENCE_ASYNC();
        attn_issue_S(tmem, ab, 0);
        TCGEN05_COMMIT(sb + 8);
    }

    int ps = 0, po = 0;
    float inv_prev = 0.f;

    for (int t = 0; t < ATT_QT; ++t) {
        int qbase = (qg*ATT_QT + t)*128;

        MBARRIER_WAIT_PARITY(sb + 8, ps); ps ^= 1;
        TCGEN05_FENCE_AFTER();
        float s[96];
#pragma unroll
        for (int cb = 0; cb < 3; ++cb) {
            uint32_t rr[32];
            TCGEN05_LD_32X32B_X32(rr, tmem + (t & 1)*96 + cb*32);
            TCGEN05_WAIT_LD();
#pragma unroll
            for (int i = 0; i < 32; ++i) s[cb*32 + i] = __uint_as_float(rr[i]);
        }
        TCGEN05_FENCE_BEFORE();

        if (t + 1 < ATT_QT) {
            size_t qrow = (size_t)(b*NQ + qbase + 128 + tid)*INNER + h*DHEAD;
            const uint4* qh = (const uint4*)(g_qhi + qrow);
            const uint4* ql = (const uint4*)(g_qlo + qrow);
            uint32_t qoff = A_Q0 + (uint32_t)((t + 1) & 1)*32768;
#pragma unroll
            for (int v = 0; v < 8; ++v) {
                uint32_t so = SMEM_SWIZZLE_128B((uint32_t)(tid*128 + v*16));
                *(uint4*)(abp + qoff + so) = qh[v];
                *(uint4*)(abp + qoff + 16384 + so) = ql[v];
            }
            __syncthreads();
            if (wid == 0 && elect_one_pred()) {
                FENCE_ASYNC();
                attn_issue_S(tmem, ab, t + 1);
                TCGEN05_COMMIT(sb + 8);
            }
        }

        int fg = g_fg[b*NQ + qbase + tid];
        float mx = -FLT_MAX;
#pragma unroll
        for (int j = 0; j < CTX; ++j) {
            float a = s[j] * 0.125f;
            bool valid = (j < 77) || ((j < 81) ? (fg != 0) : (fg == 0));
            a = valid ? a : -FLT_MAX;
            s[j] = a;
            mx = fmaxf(mx, a);
        }
        float sum = 0.f;
#pragma unroll
        for (int j = 0; j < CTX; ++j) {
            float e = (s[j] > -3.0e38f) ? __expf(s[j] - mx) : 0.f;
            s[j] = e;
            sum += e;
        }
        float inv = 1.f / sum;
#pragma unroll
        for (int j = CTX; j < 96; ++j) s[j] = 0.f;

        if (t >= 1) {
            MBARRIER_WAIT_PARITY(sb + 16, po); po ^= 1;
            TCGEN05_FENCE_AFTER();
            size_t obase = (size_t)(b*NQ + qbase - 128 + tid)*INNER + h*DHEAD;
#pragma unroll
            for (int cb = 0; cb < 2; ++cb) {
                uint32_t rr[32];
                TCGEN05_LD_32X32B_X32(rr, tmem + 192 + ((t - 1) & 1)*64 + cb*32);
                TCGEN05_WAIT_LD();
#pragma unroll
                for (int g = 0; g < 4; ++g) {
                    uint32_t hv[4], lv[4];
#pragma unroll
                    for (int pe = 0; pe < 4; ++pe) {
                        float f0 = __uint_as_float(rr[g*8 + 2*pe])     * inv_prev;
                        float f1 = __uint_as_float(rr[g*8 + 2*pe + 1]) * inv_prev;
                        ushort_t h0, l0, h1, l1;
                        bf16split(f0, h0, l0);
                        bf16split(f1, h1, l1);
                        hv[pe] = ((uint32_t)h1 << 16) | h0;
                        lv[pe] = ((uint32_t)l1 << 16) | l0;
                    }
                    *(uint4*)(g_ao_hi + obase + cb*32 + g*8) = make_uint4(hv[0], hv[1], hv[2], hv[3]);
                    *(uint4*)(g_ao_lo + obase + cb*32 + g*8) = make_uint4(lv[0], lv[1], lv[2], lv[3]);
                }
            }
            TCGEN05_FENCE_BEFORE();
        }

        {
            int r = tid;
#pragma unroll
            for (int g = 0; g < 16; ++g) {
                int c0 = g*8;
                uint32_t hv[4], lv[4];
#pragma unroll
                for (int pe = 0; pe < 4; ++pe) {
                    int c = c0 + 2*pe;
                    float f0 = (c < 96) ? s[c] : 0.f;
                    float f1 = (c+1 < 96) ? s[c+1] : 0.f;
                    ushort_t h0, l0, h1, l1;
                    bf16split(f0, h0, l0);
                    bf16split(f1, h1, l1);
                    hv[pe] = ((uint32_t)h1 << 16) | h0;
                    lv[pe] = ((uint32_t)l1 << 16) | l0;
                }
                uint32_t addr = (uint32_t)(((r >> 3) + (c0 >> 6)*16)*1024 + (r & 7)*128 + (c0 & 63)*2);
                uint32_t so = SMEM_SWIZZLE_128B(addr);
                *(uint4*)(abp + A_PHI + so) = make_uint4(hv[0], hv[1], hv[2], hv[3]);
                *(uint4*)(abp + A_PLO + so) = make_uint4(lv[0], lv[1], lv[2], lv[3]);
            }
        }
        __syncthreads();
        if (wid == 0 && elect_one_pred()) {
            FENCE_ASYNC();
            attn_issue_O(tmem, ab, t);
            TCGEN05_COMMIT(sb + 16);
        }
        inv_prev = inv;
    }

    MBARRIER_WAIT_PARITY(sb + 16, po);
    TCGEN05_FENCE_AFTER();
    {
        int qbase = (qg*ATT_QT + ATT_QT - 1)*128;
        size_t obase = (size_t)(b*NQ + qbase + tid)*INNER + h*DHEAD;
#pragma unroll
        for (int cb = 0; cb < 2; ++cb) {
            uint32_t rr[32];
            TCGEN05_LD_32X32B_X32(rr, tmem + 192 + ((ATT_QT - 1) & 1)*64 + cb*32);
            TCGEN05_WAIT_LD();
#pragma unroll
            for (int g = 0; g < 4; ++g) {
                uint32_t hv[4], lv[4];
#pragma unroll
                for (int pe = 0; pe < 4; ++pe) {
                    float f0 = __uint_as_float(rr[g*8 + 2*pe])     * inv_prev;
                    float f1 = __uint_as_float(rr[g*8 + 2*pe + 1]) * inv_prev;
                    ushort_t h0, l0, h1, l1;
                    bf16split(f0, h0, l0);
                    bf16split(f1, h1, l1);
                    hv[pe] = ((uint32_t)h1 << 16) | h0;
                    lv[pe] = ((uint32_t)l1 << 16) | l0;
                }
                *(uint4*)(g_ao_hi + obase + cb*32 + g*8) = make_uint4(hv[0], hv[1], hv[2], hv[3]);
                *(uint4*)(g_ao_lo + obase + cb*32 + g*8) = make_uint4(lv[0], lv[1], lv[2], lv[3]);
            }
        }
        TCGEN05_FENCE_BEFORE();
    }
    __syncthreads();
    if (wid == 0) TCGEN05_DEALLOC(tmem, 512);
#endif
}

// ---------------- persistent stream/event pool (created once, pre-capture) ----
struct LaunchCtx {
    cudaStream_t s2, s3;
    cudaEvent_t evFork, evSide, evQ0, evQ1, evA0, evA1;
    LaunchCtx() {
        cudaStreamCreateWithFlags(&s2, cudaStreamNonBlocking);
        cudaStreamCreateWithFlags(&s3, cudaStreamNonBlocking);
        cudaEventCreateWithFlags(&evFork, cudaEventDisableTiming);
        cudaEventCreateWithFlags(&evSide, cudaEventDisableTiming);
        cudaEventCreateWithFlags(&evQ0,  cudaEventDisableTiming);
        cudaEventCreateWithFlags(&evQ1,  cudaEventDisableTiming);
        cudaEventCreateWithFlags(&evA0,  cudaEventDisableTiming);
        cudaEventCreateWithFlags(&evA1,  cudaEventDisableTiming);
    }
};
static LaunchCtx& get_ctx() { static LaunchCtx c; return c; }

// ---------------- launch ------------------------------------------------------
extern "C" void kernel_launch(void* const* d_in, const int* in_sizes, int n_in,
                              void* d_out, int out_size)
{
    (void)in_sizes; (void)n_in; (void)out_size;
    const float* x    = (const float*)d_in[0];
    const float* ctxp = (const float*)d_in[1];
    const float* Wq   = (const float*)d_in[2];
    const float* Wk   = (const float*)d_in[3];
    const float* Wv   = (const float*)d_in[4];
    const float* Wo   = (const float*)d_in[5];
    const float* bo   = (const float*)d_in[6];
    const int*   mask = (const int*)d_in[7];
    float* out = (float*)d_out;

    float *kv;
    __nv_bfloat16 *qhi, *qlo, *aohi, *aolo;
    __nv_bfloat16 *wqth, *wqtl, *wkvth, *wkvtl, *woth, *wotl;
    cudaGetSymbolAddress((void**)&kv,    g_kv);
    cudaGetSymbolAddress((void**)&qhi,   g_qhi);
    cudaGetSymbolAddress((void**)&qlo,   g_qlo);
    cudaGetSymbolAddress((void**)&aohi,  g_ao_hi);
    cudaGetSymbolAddress((void**)&aolo,  g_ao_lo);
    cudaGetSymbolAddress((void**)&wqth,  g_wqt_hi);
    cudaGetSymbolAddress((void**)&wqtl,  g_wqt_lo);
    cudaGetSymbolAddress((void**)&wkvth, g_wkvt_hi);
    cudaGetSymbolAddress((void**)&wkvtl, g_wkvt_lo);
    cudaGetSymbolAddress((void**)&woth,  g_wot_hi);
    cudaGetSymbolAddress((void**)&wotl,  g_wot_lo);

    cudaFuncSetAttribute(gemm_bf16x3, cudaFuncAttributeMaxDynamicSharedMemorySize, G_SMEM);
    cudaFuncSetAttribute(attn_tc, cudaFuncAttributeMaxDynamicSharedMemorySize, ATTN_SMEM);

    LaunchCtx& cx = get_ctx();   // created on first (uncaptured) call only

    dim3 blk(32, 8);
    const dim3 gemm_half_grid(INNER/G_BN, MHALF/G_BM);
    const dim3 ogemm_half_grid(QD/G_BN, MHALF/G_BM);
    const dim3 attn_half_grid(NQ/(ATT_QT*128), NHEADS, BB/2);

    cudaEventRecord(cx.evFork, 0);
    cudaStreamWaitEvent(cx.s2, cx.evFork, 0);

    // side chain on s2: mask, KV weights, KV GEMM, KV images
    mask_kernel<<<(BB*NQ + 255)/256, 256, 0, cx.s2>>>(mask);
    wtrans_kernel<<<dim3(CD/32, INNER/32), blk, 0, cx.s2>>>(Wk, wkvth, wkvtl, CD, INNER);
    wtrans_kernel<<<dim3(CD/32, INNER/32), blk, 0, cx.s2>>>(
        Wv, wkvth + (size_t)INNER*CD, wkvtl + (size_t)INNER*CD, CD, INNER);
    wtrans_kernel<<<dim3(INNER/32, QD/32), blk, 0, cx.s2>>>(Wo, woth, wotl, INNER, QD);
    gemm_bf16x3<<<dim3(KVN/G_BN, MKV/G_BM), 256, G_SMEM, cx.s2>>>(
        ctxp, nullptr, nullptr, wkvth, wkvtl, nullptr, kv, nullptr, nullptr,
        BB*CTX, KVN, CD);
    kv_image_kernel<<<NBH, 128, 0, cx.s2>>>();
    cudaEventRecord(cx.evSide, cx.s2);

    // main chain: Wq transpose, then Q GEMM in batch halves
    wtrans_kernel<<<dim3(QD/32, INNER/32), blk>>>(Wq, wqth, wqtl, QD, INNER);
    gemm_bf16x3<<<gemm_half_grid, 256, G_SMEM>>>(
        x, nullptr, nullptr, wqth, wqtl, nullptr, nullptr, qhi, qlo,
        MHALF, INNER, QD);
    cudaEventRecord(cx.evQ0, 0);
    gemm_bf16x3<<<gemm_half_grid, 256, G_SMEM>>>(
        x + (size_t)MHALF*QD, nullptr, nullptr, wqth, wqtl, nullptr, nullptr,
        qhi + (size_t)MHALF*INNER, qlo + (size_t)MHALF*INNER,
        MHALF, INNER, QD);
    cudaEventRecord(cx.evQ1, 0);

    // attention halves on s3, each waiting on its Q half (+ side chain)
    cudaStreamWaitEvent(cx.s3, cx.evQ0, 0);
    cudaStreamWaitEvent(cx.s3, cx.evSide, 0);
    attn_tc<<<attn_half_grid, 128, ATTN_SMEM, cx.s3>>>(0);
    cudaEventRecord(cx.evA0, cx.s3);
    cudaStreamWaitEvent(cx.s3, cx.evQ1, 0);
    attn_tc<<<attn_half_grid, 128, ATTN_SMEM, cx.s3>>>(BB/2);
    cudaEventRecord(cx.evA1, cx.s3);

    // output projection halves on capture stream
    cudaStreamWaitEvent(0, cx.evA0, 0);
    gemm_bf16x3<<<ogemm_half_grid, 256, G_SMEM>>>(
        nullptr, aohi, aolo, woth, wotl, bo, out, nullptr, nullptr,
        MHALF, QD, INNER);
    cudaStreamWaitEvent(0, cx.evA1, 0);
    gemm_bf16x3<<<ogemm_half_grid, 256, G_SMEM>>>(
        nullptr, aohi + (size_t)MHALF*INNER, aolo + (size_t)MHALF*INNER,
        woth, wotl, bo, out + (size_t)MHALF*QD, nullptr, nullptr,
        MHALF, QD, INNER);
}

// round 17
// speedup vs baseline: 1.0259x; 1.0259x over previous
#include <cuda_runtime.h>
#include <cuda_bf16.h>
#include <math.h>
#include <float.h>
#include <stdint.h>

#define BB 8
#define NQ 4096
#define QD 1280
#define CD 1024
#define CTX 85
#define NHEADS 20
#define DHEAD 64
#define INNER (NHEADS*DHEAD)   // 1280
#define KVN (2*INNER)          // 2560
#define MKV 768
#define NBH (BB*NHEADS)        // 160
#define MHALF (BB*NQ/2)        // 16384

typedef unsigned short ushort_t;

// ---------------- scratch (static device globals; no allocation) -------------
__device__ float g_kv[(size_t)MKV*KVN];
__device__ __nv_bfloat16 g_qhi[(size_t)BB*NQ*INNER];
__device__ __nv_bfloat16 g_qlo[(size_t)BB*NQ*INNER];
__device__ __nv_bfloat16 g_ao_hi[(size_t)BB*NQ*INNER];
__device__ __nv_bfloat16 g_ao_lo[(size_t)BB*NQ*INNER];
__device__ __nv_bfloat16 g_wqt_hi[(size_t)INNER*QD];
__device__ __nv_bfloat16 g_wqt_lo[(size_t)INNER*QD];
__device__ __nv_bfloat16 g_wkvt_hi[(size_t)KVN*CD];
__device__ __nv_bfloat16 g_wkvt_lo[(size_t)KVN*CD];
__device__ __nv_bfloat16 g_wot_hi[(size_t)QD*INNER];
__device__ __nv_bfloat16 g_wot_lo[(size_t)QD*INNER];
__device__ __nv_bfloat16 g_kimg_hi[(size_t)NBH*96*64];
__device__ __nv_bfloat16 g_kimg_lo[(size_t)NBH*96*64];
__device__ __nv_bfloat16 g_vimg_hi[(size_t)NBH*64*128];
__device__ __nv_bfloat16 g_vimg_lo[(size_t)NBH*64*128];
__device__ unsigned char g_fg[BB*NQ];

// ============================ PTX helpers ====================================
__device__ __forceinline__ uint32_t smem_to_u32(const void* p) {
    uint32_t a;
    asm("{ .reg .u64 t; cvta.to.shared.u64 t, %1; cvt.u32.u64 %0, t; }"
        : "=r"(a) : "l"(p));
    return a;
}

#if defined(__CUDA_ARCH_FEAT_SM103_ALL)
#define HAS_TCGEN05 1
#else
#define HAS_TCGEN05 0
#endif

#if HAS_TCGEN05
__device__ __forceinline__ uint32_t elect_one_pred() {
    uint32_t pred;
    asm volatile(
        "{\n\t.reg .pred p;\n\t"
        "elect.sync _|p, 0xFFFFFFFF;\n\t"
        "selp.b32 %0, 1, 0, p;\n\t}"
        : "=r"(pred));
    return pred;
}
#define TCGEN05_ALLOC(sa, n) \
    asm volatile("tcgen05.alloc.cta_group::1.sync.aligned.shared::cta.b32 [%0], %1;" \
        :: "r"((uint32_t)(sa)), "r"((uint32_t)(n)) : "memory")
#define TCGEN05_DEALLOC(t, n) \
    asm volatile("tcgen05.dealloc.cta_group::1.sync.aligned.b32 %0, %1;" :: "r"(t), "r"((uint32_t)(n)))
#define TCGEN05_RELINQ() \
    asm volatile("tcgen05.relinquish_alloc_permit.cta_group::1.sync.aligned;")
#define TCGEN05_COMMIT(mb) \
    asm volatile("tcgen05.commit.cta_group::1.mbarrier::arrive::one.shared::cluster.b64 [%0];" \
        :: "r"((uint32_t)(mb)) : "memory")
#define TCGEN05_FENCE_AFTER() asm volatile("tcgen05.fence::after_thread_sync;" ::: "memory")
#define TCGEN05_FENCE_BEFORE() asm volatile("tcgen05.fence::before_thread_sync;" ::: "memory")
#define TCGEN05_WAIT_LD() asm volatile("tcgen05.wait::ld.sync.aligned;" ::: "memory")
#define FENCE_ASYNC() asm volatile("fence.proxy.async.shared::cta;" ::: "memory")
#define MBARRIER_INIT(mb, c) \
    asm volatile("mbarrier.init.shared.b64 [%0], %1;" :: "r"((uint32_t)(mb)), "r"((uint32_t)(c)) : "memory")
#define MBARRIER_WAIT_PARITY(mb, ph) do { \
    uint32_t _m = (uint32_t)(mb), _p = (uint32_t)(ph), _d; \
    asm volatile("{\n\t.reg .pred p;\n\t" \
        "mbarrier.try_wait.parity.acquire.cta.shared::cta.b64 p, [%1], %2;\n\t" \
        "selp.b32 %0, 1, 0, p;\n\t}" : "=r"(_d) : "r"(_m), "r"(_p) : "memory"); \
    if (!_d) { \
        asm volatile("{\n\t.reg .pred P1;\n\t" \
            "WL_%=:\n\t" \
            "mbarrier.try_wait.parity.acquire.cta.shared::cta.b64 P1, [%0], %1, 0x989680;\n\t" \
            "@P1 bra.uni WD_%=;\n\t" \
            "bra.uni WL_%=;\n\t" \
            "WD_%=:\n\t}" :: "r"(_m), "r"(_p) : "memory"); \
    } \
} while (0)
#define TCGEN05_LD_32X32B_X32(r, ta) \
    asm volatile("tcgen05.ld.sync.aligned.32x32b.x32.b32 " \
        "{%0, %1, %2, %3, %4, %5, %6, %7, %8, %9, %10, %11, %12, %13, %14, %15, " \
        " %16, %17, %18, %19, %20, %21, %22, %23, %24, %25, %26, %27, %28, %29, %30, %31}, [%32];" \
        : "=r"((r)[0]),  "=r"((r)[1]),  "=r"((r)[2]),  "=r"((r)[3]), \
          "=r"((r)[4]),  "=r"((r)[5]),  "=r"((r)[6]),  "=r"((r)[7]), \
          "=r"((r)[8]),  "=r"((r)[9]),  "=r"((r)[10]), "=r"((r)[11]), \
          "=r"((r)[12]), "=r"((r)[13]), "=r"((r)[14]), "=r"((r)[15]), \
          "=r"((r)[16]), "=r"((r)[17]), "=r"((r)[18]), "=r"((r)[19]), \
          "=r"((r)[20]), "=r"((r)[21]), "=r"((r)[22]), "=r"((r)[23]), \
          "=r"((r)[24]), "=r"((r)[25]), "=r"((r)[26]), "=r"((r)[27]), \
          "=r"((r)[28]), "=r"((r)[29]), "=r"((r)[30]), "=r"((r)[31]) \
        : "r"(ta))

__device__ __forceinline__ void mma_f16_ss(uint32_t d_tmem, uint64_t a_desc,
                                           uint64_t b_desc, uint32_t idesc, bool acc)
{
    uint32_t en = acc ? 1u : 0u;
    asm volatile(
        "{\n\t.reg .pred p;\n\t"
        "setp.ne.u32 p, %5, 0;\n\t"
        "tcgen05.mma.cta_group::1.kind::f16 [%0], %1, %2, %3, {%4, %4, %4, %4}, p;\n\t}"
        :: "r"(d_tmem), "l"(a_desc), "l"(b_desc), "r"(idesc), "r"(0u), "r"(en)
        : "memory");
}
#endif // HAS_TCGEN05

static constexpr uint64_t SMEM_DESC_BASE_SW128 =
    (uint64_t(2)  << 61) | (uint64_t(1) << 46) | (uint64_t(64) << 32) | (uint64_t(1) << 16);
#define MAKE_SMEM_DESC(ba) (SMEM_DESC_BASE_SW128 | ((uint64_t)((ba) >> 4) & 0x3FFF))
#define SMEM_SWIZZLE_128B(bo) ((bo) ^ (((bo) >> 3) & 0x70))

__device__ __forceinline__ void bf16split(float f, ushort_t& h, ushort_t& l)
{
    __nv_bfloat16 hh = __float2bfloat16(f);
    __nv_bfloat16 ll = __float2bfloat16(f - __bfloat162float(hh));
    h = __bfloat16_as_ushort(hh);
    l = __bfloat16_as_ushort(ll);
}

// ---------------- mask: exact integer bicubic-threshold ----------------------
__global__ void mask_kernel(const int* __restrict__ mask)
{
    int idx = blockIdx.x * blockDim.x + threadIdx.x;
    if (idx >= BB*NQ) return;
    int b = idx / NQ, n = idx % NQ;
    int o = n >> 6, p = n & 63;
    const int iw[4] = {-3, 19, 19, -3};
    const int* mb = mask + (size_t)b * 256 * 256;
    int acc = 0;
#pragma unroll
    for (int s = 0; s < 4; s++) {
        const int* row = mb + (4*o + s) * 256 + 4*p;
        int rw = iw[s];
#pragma unroll
        for (int t = 0; t < 4; t++) acc += rw * iw[t] * row[t];
    }
    g_fg[idx] = (acc != 0) ? 1 : 0;
}

// ---------------- weight transpose + bf16 split -------------------------------
__global__ void wtrans_kernel(const float* __restrict__ W,
                              __nv_bfloat16* __restrict__ Thi,
                              __nv_bfloat16* __restrict__ Tlo, int K, int N)
{
    __shared__ float t[32][33];
    int k0 = blockIdx.x * 32, n0 = blockIdx.y * 32;
    int tx = threadIdx.x, ty = threadIdx.y;
    for (int r = ty; r < 32; r += 8)
        t[r][tx] = W[(size_t)(k0 + r)*N + n0 + tx];
    __syncthreads();
    for (int r = ty; r < 32; r += 8) {
        float v = t[tx][r];
        ushort_t h, l; bf16split(v, h, l);
        Thi[(size_t)(n0 + r)*K + k0 + tx] = __ushort_as_bfloat16(h);
        Tlo[(size_t)(n0 + r)*K + k0 + tx] = __ushort_as_bfloat16(l);
    }
}

// ================= bf16x3 tcgen05 GEMM: C = A@B^T (+bias) ====================
#define G_BM 128
#define G_BN 256
#define G_BK 64
#define G_BUFSZ 98304
#define G_SMEM  (2048 + 2*G_BUFSZ)
#define G_IDESC 0x08400490u   // F32 acc, BF16xBF16, N=256, M=128

__global__ void __launch_bounds__(256)
gemm_bf16x3(const float* __restrict__ Af,
            const __nv_bfloat16* __restrict__ Ahi, const __nv_bfloat16* __restrict__ Alo,
            const __nv_bfloat16* __restrict__ Bhi, const __nv_bfloat16* __restrict__ Blo,
            const float* __restrict__ bias, float* __restrict__ C,
            __nv_bfloat16* __restrict__ Chi, __nv_bfloat16* __restrict__ Clo,
            int Mvalid, int N, int K)
{
#if HAS_TCGEN05
    extern __shared__ char smem[];
    const uint32_t sb = smem_to_u32(smem);
    const uint32_t ab = (sb + 1024 + 1023) & ~1023u;
    char* abp = smem + (ab - sb);
    const int tid = threadIdx.x;
    const int wid = tid >> 5, lane = tid & 31;
    const int brow = blockIdx.y * G_BM;
    const int bcol = blockIdx.x * G_BN;

    if (wid == 0) TCGEN05_ALLOC(sb, 256);
    __syncthreads();
    uint32_t tmem;
    asm volatile("ld.shared.b32 %0, [%1];" : "=r"(tmem) : "r"(sb));
    if (wid == 0) TCGEN05_RELINQ();
    if (tid == 0) { MBARRIER_INIT(sb + 8, 1); MBARRIER_INIT(sb + 16, 1); }
    __syncthreads();

    const int KCH = K / G_BK;
    int par0 = 0, par1 = 0;

    uint4 pa0[4], pa1[4], pbh[8], pbl[8];
    const int a_row = tid >> 3;
    const int a_v   = tid & 7;

    auto load_chunk = [&](int c) {
        const int k0 = c * G_BK;
        if (Af) {
#pragma unroll
            for (int i = 0; i < 4; ++i) {
                int gr = brow + a_row + i*32;
                if (gr < Mvalid) {
                    const uint4* src = (const uint4*)(Af + (size_t)gr*K + k0 + a_v*8);
                    pa0[i] = src[0];
                    pa1[i] = src[1];
                } else {
                    pa0[i] = make_uint4(0u,0u,0u,0u);
                    pa1[i] = make_uint4(0u,0u,0u,0u);
                }
            }
        } else {
#pragma unroll
            for (int i = 0; i < 4; ++i) {
                int gr = brow + a_row + i*32;
                pa0[i] = *(const uint4*)(Ahi + (size_t)gr*K + k0 + a_v*8);
                pa1[i] = *(const uint4*)(Alo + (size_t)gr*K + k0 + a_v*8);
            }
        }
#pragma unroll
        for (int i = 0; i < 8; ++i) {
            int row = a_row + i*32;
            pbh[i] = *(const uint4*)(Bhi + (size_t)(bcol + row)*K + k0 + a_v*8);
            pbl[i] = *(const uint4*)(Blo + (size_t)(bcol + row)*K + k0 + a_v*8);
        }
    };

    load_chunk(0);

    for (int c = 0; c < KCH; ++c) {
        int p = c & 1;
        if (c >= 2) {
            if (p == 0) { MBARRIER_WAIT_PARITY(sb + 8, par0); par0 ^= 1; }
            else        { MBARRIER_WAIT_PARITY(sb + 16, par1); par1 ^= 1; }
        }
        char* base = abp + p * G_BUFSZ;

#pragma unroll
        for (int i = 0; i < 4; ++i) {
            uint32_t so = SMEM_SWIZZLE_128B((uint32_t)((a_row + i*32)*128 + a_v*16));
            uint4 vh, vl;
            if (Af) {
                const float* f0 = (const float*)&pa0[i];
                const float* f1 = (const float*)&pa1[i];
                float fa[8] = {f0[0], f0[1], f0[2], f0[3], f1[0], f1[1], f1[2], f1[3]};
                uint32_t hw[4], lw[4];
#pragma unroll
                for (int e = 0; e < 4; ++e) {
                    ushort_t h0, l0, h1, l1;
                    bf16split(fa[2*e],   h0, l0);
                    bf16split(fa[2*e+1], h1, l1);
                    hw[e] = ((uint32_t)h1 << 16) | h0;
                    lw[e] = ((uint32_t)l1 << 16) | l0;
                }
                vh = make_uint4(hw[0], hw[1], hw[2], hw[3]);
                vl = make_uint4(lw[0], lw[1], lw[2], lw[3]);
            } else {
                vh = pa0[i];
                vl = pa1[i];
            }
            *(uint4*)(base + so) = vh;
            *(uint4*)(base + 16384 + so) = vl;
        }
#pragma unroll
        for (int i = 0; i < 8; ++i) {
            uint32_t so = SMEM_SWIZZLE_128B((uint32_t)((a_row + i*32)*128 + a_v*16));
            *(uint4*)(base + 32768 + so) = pbh[i];
            *(uint4*)(base + 65536 + so) = pbl[i];
        }
        __syncthreads();

        if (wid == 0 && elect_one_pred()) {
            FENCE_ASYNC();
            uint32_t bu = ab + p * G_BUFSZ;
            uint64_t dah = MAKE_SMEM_DESC(bu);
            uint64_t dal = MAKE_SMEM_DESC(bu + 16384);
            uint64_t dbh = MAKE_SMEM_DESC(bu + 32768);
            uint64_t dbl = MAKE_SMEM_DESC(bu + 65536);
#pragma unroll
            for (int ks = 0; ks < 4; ++ks)
                mma_f16_ss(tmem, dah + ks*2, dbh + ks*2, G_IDESC, !(c == 0 && ks == 0));
#pragma unroll
            for (int ks = 0; ks < 4; ++ks)
                mma_f16_ss(tmem, dah + ks*2, dbl + ks*2, G_IDESC, true);
#pragma unroll
            for (int ks = 0; ks < 4; ++ks)
                mma_f16_ss(tmem, dal + ks*2, dbh + ks*2, G_IDESC, true);
            TCGEN05_COMMIT(sb + 8 + p*8);
        }

        if (c + 1 < KCH) load_chunk(c + 1);
    }
    MBARRIER_WAIT_PARITY(sb + 8, par0);
    MBARRIER_WAIT_PARITY(sb + 16, par1);
    TCGEN05_FENCE_AFTER();

    if (wid < 4) {
        int row = brow + wid*32 + lane;
#pragma unroll
        for (int cb = 0; cb < G_BN/32; ++cb) {
            uint32_t r[32];
            TCGEN05_LD_32X32B_X32(r, tmem + cb*32);
            TCGEN05_WAIT_LD();
            int col0 = bcol + cb*32;
            if (Chi) {
                uint32_t hp[16], lp[16];
#pragma unroll
                for (int m = 0; m < 16; ++m) {
                    ushort_t h0, l0, h1, l1;
                    bf16split(__uint_as_float(r[2*m]),   h0, l0);
                    bf16split(__uint_as_float(r[2*m+1]), h1, l1);
                    hp[m] = ((uint32_t)h1 << 16) | h0;
                    lp[m] = ((uint32_t)l1 << 16) | l0;
                }
                uint32_t* dh = (uint32_t*)(Chi + (size_t)row*N + col0);
                uint32_t* dl = (uint32_t*)(Clo + (size_t)row*N + col0);
#pragma unroll
                for (int m = 0; m < 16; ++m) { dh[m] = hp[m]; dl[m] = lp[m]; }
            } else {
                float* cp = C + (size_t)row*N + col0;
                if (bias) {
#pragma unroll
                    for (int i = 0; i < 32; ++i) cp[i] = __uint_as_float(r[i]) + bias[col0 + i];
                } else {
#pragma unroll
                    for (int i = 0; i < 32; ++i) cp[i] = __uint_as_float(r[i]);
                }
            }
        }
        TCGEN05_FENCE_BEFORE();
    }
    __syncthreads();
    if (wid == 0) TCGEN05_DEALLOC(tmem, 256);
#endif
}

// ---------------- K / V^T image bake (from merged g_kv) -----------------------
__global__ void __launch_bounds__(128) kv_image_kernel()
{
    int bh = blockIdx.x;
    int b = bh / NHEADS, h = bh % NHEADS;
    int tid = threadIdx.x;
    char* kh = (char*)(g_kimg_hi + (size_t)bh*96*64);
    char* kl = (char*)(g_kimg_lo + (size_t)bh*96*64);
    char* vh = (char*)(g_vimg_hi + (size_t)bh*64*128);
    char* vl = (char*)(g_vimg_lo + (size_t)bh*64*128);

    for (int u = tid; u < 96*64; u += 128) {
        int j = u >> 6, d = u & 63;
        float f = (j < CTX) ? g_kv[(size_t)(b*CTX + j)*KVN + h*DHEAD + d] : 0.f;
        ushort_t hh, ll; bf16split(f, hh, ll);
        uint32_t so = SMEM_SWIZZLE_128B((uint32_t)(j*128 + d*2));
        *(ushort_t*)(kh + so) = hh;
        *(ushort_t*)(kl + so) = ll;
    }
    for (int u = tid; u < 64*128; u += 128) {
        int d = u >> 7, j = u & 127;
        float f = (j < CTX) ? g_kv[(size_t)(b*CTX + j)*KVN + INNER + h*DHEAD + d] : 0.f;
        ushort_t hh, ll; bf16split(f, hh, ll);
        uint32_t addr = (uint32_t)(((d >> 3) + (j >> 6)*8)*1024 + (d & 7)*128 + (j & 63)*2);
        uint32_t so = SMEM_SWIZZLE_128B(addr);
        *(ushort_t*)(vh + so) = hh;
        *(ushort_t*)(vl + so) = ll;
    }
}

// ---------------- tcgen05 fused masked attention (pipelined) ------------------
#define ATT_QT 8
#define A_KHI 0
#define A_KLO 12288
#define A_VHI 24576
#define A_VLO 40960
#define A_Q0  57344
#define A_PHI 122880
#define A_PLO 155648
#define ATTN_SMEM (2048 + 188416)
#define IDESC_S 0x08180490u
#define IDESC_O 0x08100490u

#if HAS_TCGEN05
__device__ __forceinline__ void attn_issue_S(uint32_t tmem, uint32_t ab, int t)
{
    uint32_t qb = ab + A_Q0 + (uint32_t)(t & 1)*32768;
    uint64_t dqh = MAKE_SMEM_DESC(qb);
    uint64_t dql = MAKE_SMEM_DESC(qb + 16384);
    uint64_t dkh = MAKE_SMEM_DESC(ab + A_KHI);
    uint64_t dkl = MAKE_SMEM_DESC(ab + A_KLO);
    uint32_t dst = tmem + (uint32_t)(t & 1)*96;
#pragma unroll
    for (int ks = 0; ks < 4; ++ks)
        mma_f16_ss(dst, dqh + ks*2, dkh + ks*2, IDESC_S, ks > 0);
#pragma unroll
    for (int ks = 0; ks < 4; ++ks)
        mma_f16_ss(dst, dqh + ks*2, dkl + ks*2, IDESC_S, true);
#pragma unroll
    for (int ks = 0; ks < 4; ++ks)
        mma_f16_ss(dst, dql + ks*2, dkh + ks*2, IDESC_S, true);
}

__device__ __forceinline__ void attn_issue_O(uint32_t tmem, uint32_t ab, int t)
{
    uint64_t dph = MAKE_SMEM_DESC(ab + A_PHI);
    uint64_t dpl = MAKE_SMEM_DESC(ab + A_PLO);
    uint64_t dvh = MAKE_SMEM_DESC(ab + A_VHI);
    uint64_t dvl = MAKE_SMEM_DESC(ab + A_VLO);
    uint32_t dst = tmem + 192 + (uint32_t)(t & 1)*64;
#pragma unroll
    for (int ks = 0; ks < 8; ++ks) {
        uint64_t aoff = (ks < 4) ? ks*2 : 1024 + (ks-4)*2;
        uint64_t boff = (ks < 4) ? ks*2 : 512 + (ks-4)*2;
        mma_f16_ss(dst, dph + aoff, dvh + boff, IDESC_O, ks > 0);
    }
#pragma unroll
    for (int ks = 0; ks < 8; ++ks) {
        uint64_t aoff = (ks < 4) ? ks*2 : 1024 + (ks-4)*2;
        uint64_t boff = (ks < 4) ? ks*2 : 512 + (ks-4)*2;
        mma_f16_ss(dst, dph + aoff, dvl + boff, IDESC_O, true);
    }
#pragma unroll
    for (int ks = 0; ks < 8; ++ks) {
        uint64_t aoff = (ks < 4) ? ks*2 : 1024 + (ks-4)*2;
        uint64_t boff = (ks < 4) ? ks*2 : 512 + (ks-4)*2;
        mma_f16_ss(dst, dpl + aoff, dvh + boff, IDESC_O, true);
    }
}
#endif

__global__ void __launch_bounds__(128) attn_tc(int b_off)
{
#if HAS_TCGEN05
    extern __shared__ char smem[];
    const uint32_t sb = smem_to_u32(smem);
    const uint32_t ab = (sb + 1024 + 1023) & ~1023u;
    char* abp = smem + (ab - sb);
    int tid = threadIdx.x, wid = tid >> 5;
    int b = blockIdx.z + b_off, h = blockIdx.y, qg = blockIdx.x;
    int bh = b*NHEADS + h;

    if (wid == 0) TCGEN05_ALLOC(sb, 512);
    __syncthreads();
    uint32_t tmem;
    asm volatile("ld.shared.b32 %0, [%1];" : "=r"(tmem) : "r"(sb));
    if (wid == 0) TCGEN05_RELINQ();
    if (tid == 0) { MBARRIER_INIT(sb + 8, 1); MBARRIER_INIT(sb + 16, 1); }
    __syncthreads();

    {
        const uint4* skh = (const uint4*)(g_kimg_hi + (size_t)bh*96*64);
        const uint4* skl = (const uint4*)(g_kimg_lo + (size_t)bh*96*64);
        for (int u = tid; u < 768; u += 128) {
            ((uint4*)(abp + A_KHI))[u] = skh[u];
            ((uint4*)(abp + A_KLO))[u] = skl[u];
        }
        const uint4* svh = (const uint4*)(g_vimg_hi + (size_t)bh*64*128);
        const uint4* svl = (const uint4*)(g_vimg_lo + (size_t)bh*64*128);
        for (int u = tid; u < 1024; u += 128) {
            ((uint4*)(abp + A_VHI))[u] = svh[u];
            ((uint4*)(abp + A_VLO))[u] = svl[u];
        }
    }
    {
        int qbase = qg*ATT_QT*128;
        size_t qrow = (size_t)(b*NQ + qbase + tid)*INNER + h*DHEAD;
        const uint4* qh = (const uint4*)(g_qhi + qrow);
        const uint4* ql = (const uint4*)(g_qlo + qrow);
#pragma unroll
        for (int v = 0; v < 8; ++v) {
            uint32_t so = SMEM_SWIZZLE_128B((uint32_t)(tid*128 + v*16));
            *(uint4*)(abp + A_Q0 + so) = qh[v];
            *(uint4*)(abp + A_Q0 + 16384 + so) = ql[v];
        }
    }
    __syncthreads();
    if (wid == 0 && elect_one_pred()) {
        FENCE_ASYNC();
        attn_issue_S(tmem, ab, 0);
        TCGEN05_COMMIT(sb + 8);
    }

    int ps = 0, po = 0;
    float inv_prev = 0.f;

    for (int t = 0; t < ATT_QT; ++t) {
        int qbase = (qg*ATT_QT + t)*128;

        MBARRIER_WAIT_PARITY(sb + 8, ps); ps ^= 1;
        TCGEN05_FENCE_AFTER();
        float s[96];
#pragma unroll
        for (int cb = 0; cb < 3; ++cb) {
            uint32_t rr[32];
            TCGEN05_LD_32X32B_X32(rr, tmem + (t & 1)*96 + cb*32);
            TCGEN05_WAIT_LD();
#pragma unroll
            for (int i = 0; i < 32; ++i) s[cb*32 + i] = __uint_as_float(rr[i]);
        }
        TCGEN05_FENCE_BEFORE();

        if (t + 1 < ATT_QT) {
            size_t qrow = (size_t)(b*NQ + qbase + 128 + tid)*INNER + h*DHEAD;
            const uint4* qh = (const uint4*)(g_qhi + qrow);
            const uint4* ql = (const uint4*)(g_qlo + qrow);
            uint32_t qoff = A_Q0 + (uint32_t)((t + 1) & 1)*32768;
#pragma unroll
            for (int v = 0; v < 8; ++v) {
                uint32_t so = SMEM_SWIZZLE_128B((uint32_t)(tid*128 + v*16));
                *(uint4*)(abp + qoff + so) = qh[v];
                *(uint4*)(abp + qoff + 16384 + so) = ql[v];
            }
            __syncthreads();
            if (wid == 0 && elect_one_pred()) {
                FENCE_ASYNC();
                attn_issue_S(tmem, ab, t + 1);
                TCGEN05_COMMIT(sb + 8);
            }
        }

        int fg = g_fg[b*NQ + qbase + tid];
        float mx = -FLT_MAX;
#pragma unroll
        for (int j = 0; j < CTX; ++j) {
            float a = s[j] * 0.125f;
            bool valid = (j < 77) || ((j < 81) ? (fg != 0) : (fg == 0));
            a = valid ? a : -FLT_MAX;
            s[j] = a;
            mx = fmaxf(mx, a);
        }
        float sum = 0.f;
#pragma unroll
        for (int j = 0; j < CTX; ++j) {
            float e = (s[j] > -3.0e38f) ? __expf(s[j] - mx) : 0.f;
            s[j] = e;
            sum += e;
        }
        float inv = 1.f / sum;
#pragma unroll
        for (int j = CTX; j < 96; ++j) s[j] = 0.f;

        if (t >= 1) {
            MBARRIER_WAIT_PARITY(sb + 16, po); po ^= 1;
            TCGEN05_FENCE_AFTER();
            size_t obase = (size_t)(b*NQ + qbase - 128 + tid)*INNER + h*DHEAD;
#pragma unroll
            for (int cb = 0; cb < 2; ++cb) {
                uint32_t rr[32];
                TCGEN05_LD_32X32B_X32(rr, tmem + 192 + ((t - 1) & 1)*64 + cb*32);
                TCGEN05_WAIT_LD();
#pragma unroll
                for (int g = 0; g < 4; ++g) {
                    uint32_t hv[4], lv[4];
#pragma unroll
                    for (int pe = 0; pe < 4; ++pe) {
                        float f0 = __uint_as_float(rr[g*8 + 2*pe])     * inv_prev;
                        float f1 = __uint_as_float(rr[g*8 + 2*pe + 1]) * inv_prev;
                        ushort_t h0, l0, h1, l1;
                        bf16split(f0, h0, l0);
                        bf16split(f1, h1, l1);
                        hv[pe] = ((uint32_t)h1 << 16) | h0;
                        lv[pe] = ((uint32_t)l1 << 16) | l0;
                    }
                    *(uint4*)(g_ao_hi + obase + cb*32 + g*8) = make_uint4(hv[0], hv[1], hv[2], hv[3]);
                    *(uint4*)(g_ao_lo + obase + cb*32 + g*8) = make_uint4(lv[0], lv[1], lv[2], lv[3]);
                }
            }
            TCGEN05_FENCE_BEFORE();
        }

        {
            int r = tid;
#pragma unroll
            for (int g = 0; g < 16; ++g) {
                int c0 = g*8;
                uint32_t hv[4], lv[4];
#pragma unroll
                for (int pe = 0; pe < 4; ++pe) {
                    int c = c0 + 2*pe;
                    float f0 = (c < 96) ? s[c] : 0.f;
                    float f1 = (c+1 < 96) ? s[c+1] : 0.f;
                    ushort_t h0, l0, h1, l1;
                    bf16split(f0, h0, l0);
                    bf16split(f1, h1, l1);
                    hv[pe] = ((uint32_t)h1 << 16) | h0;
                    lv[pe] = ((uint32_t)l1 << 16) | l0;
                }
                uint32_t addr = (uint32_t)(((r >> 3) + (c0 >> 6)*16)*1024 + (r & 7)*128 + (c0 & 63)*2);
                uint32_t so = SMEM_SWIZZLE_128B(addr);
                *(uint4*)(abp + A_PHI + so) = make_uint4(hv[0], hv[1], hv[2], hv[3]);
                *(uint4*)(abp + A_PLO + so) = make_uint4(lv[0], lv[1], lv[2], lv[3]);
            }
        }
        __syncthreads();
        if (wid == 0 && elect_one_pred()) {
            FENCE_ASYNC();
            attn_issue_O(tmem, ab, t);
            TCGEN05_COMMIT(sb + 16);
        }
        inv_prev = inv;
    }

    MBARRIER_WAIT_PARITY(sb + 16, po);
    TCGEN05_FENCE_AFTER();
    {
        int qbase = (qg*ATT_QT + ATT_QT - 1)*128;
        size_t obase = (size_t)(b*NQ + qbase + tid)*INNER + h*DHEAD;
#pragma unroll
        for (int cb = 0; cb < 2; ++cb) {
            uint32_t rr[32];
            TCGEN05_LD_32X32B_X32(rr, tmem + 192 + ((ATT_QT - 1) & 1)*64 + cb*32);
            TCGEN05_WAIT_LD();
#pragma unroll
            for (int g = 0; g < 4; ++g) {
                uint32_t hv[4], lv[4];
#pragma unroll
                for (int pe = 0; pe < 4; ++pe) {
                    float f0 = __uint_as_float(rr[g*8 + 2*pe])     * inv_prev;
                    float f1 = __uint_as_float(rr[g*8 + 2*pe + 1]) * inv_prev;
                    ushort_t h0, l0, h1, l1;
                    bf16split(f0, h0, l0);
                    bf16split(f1, h1, l1);
                    hv[pe] = ((uint32_t)h1 << 16) | h0;
                    lv[pe] = ((uint32_t)l1 << 16) | l0;
                }
                *(uint4*)(g_ao_hi + obase + cb*32 + g*8) = make_uint4(hv[0], hv[1], hv[2], hv[3]);
                *(uint4*)(g_ao_lo + obase + cb*32 + g*8) = make_uint4(lv[0], lv[1], lv[2], lv[3]);
            }
        }
        TCGEN05_FENCE_BEFORE();
    }
    __syncthreads();
    if (wid == 0) TCGEN05_DEALLOC(tmem, 512);
#endif
}

// ---------------- persistent stream/event pool (created once, pre-capture) ----
struct LaunchCtx {
    cudaStream_t s2, s3;
    cudaEvent_t evFork, evSide, evQ, evA0, evA1;
    LaunchCtx() {
        cudaStreamCreateWithFlags(&s2, cudaStreamNonBlocking);
        cudaStreamCreateWithFlags(&s3, cudaStreamNonBlocking);
        cudaEventCreateWithFlags(&evFork, cudaEventDisableTiming);
        cudaEventCreateWithFlags(&evSide, cudaEventDisableTiming);
        cudaEventCreateWithFlags(&evQ,   cudaEventDisableTiming);
        cudaEventCreateWithFlags(&evA0,  cudaEventDisableTiming);
        cudaEventCreateWithFlags(&evA1,  cudaEventDisableTiming);
    }
};
static LaunchCtx& get_ctx() { static LaunchCtx c; return c; }

// ---------------- launch ------------------------------------------------------
extern "C" void kernel_launch(void* const* d_in, const int* in_sizes, int n_in,
                              void* d_out, int out_size)
{
    (void)in_sizes; (void)n_in; (void)out_size;
    const float* x    = (const float*)d_in[0];
    const float* ctxp = (const float*)d_in[1];
    const float* Wq   = (const float*)d_in[2];
    const float* Wk   = (const float*)d_in[3];
    const float* Wv   = (const float*)d_in[4];
    const float* Wo   = (const float*)d_in[5];
    const float* bo   = (const float*)d_in[6];
    const int*   mask = (const int*)d_in[7];
    float* out = (float*)d_out;

    float *kv;
    __nv_bfloat16 *qhi, *qlo, *aohi, *aolo;
    __nv_bfloat16 *wqth, *wqtl, *wkvth, *wkvtl, *woth, *wotl;
    cudaGetSymbolAddress((void**)&kv,    g_kv);
    cudaGetSymbolAddress((void**)&qhi,   g_qhi);
    cudaGetSymbolAddress((void**)&qlo,   g_qlo);
    cudaGetSymbolAddress((void**)&aohi,  g_ao_hi);
    cudaGetSymbolAddress((void**)&aolo,  g_ao_lo);
    cudaGetSymbolAddress((void**)&wqth,  g_wqt_hi);
    cudaGetSymbolAddress((void**)&wqtl,  g_wqt_lo);
    cudaGetSymbolAddress((void**)&wkvth, g_wkvt_hi);
    cudaGetSymbolAddress((void**)&wkvtl, g_wkvt_lo);
    cudaGetSymbolAddress((void**)&woth,  g_wot_hi);
    cudaGetSymbolAddress((void**)&wotl,  g_wot_lo);

    cudaFuncSetAttribute(gemm_bf16x3, cudaFuncAttributeMaxDynamicSharedMemorySize, G_SMEM);
    cudaFuncSetAttribute(attn_tc, cudaFuncAttributeMaxDynamicSharedMemorySize, ATTN_SMEM);

    LaunchCtx& cx = get_ctx();   // created on first (uncaptured) call only

    dim3 blk(32, 8);
    const dim3 ogemm_half_grid(QD/G_BN, MHALF/G_BM);
    const dim3 attn_half_grid(NQ/(ATT_QT*128), NHEADS, BB/2);

    cudaEventRecord(cx.evFork, 0);
    cudaStreamWaitEvent(cx.s2, cx.evFork, 0);

    // side chain on s2: mask, KV weights, KV GEMM, KV images
    mask_kernel<<<(BB*NQ + 255)/256, 256, 0, cx.s2>>>(mask);
    wtrans_kernel<<<dim3(CD/32, INNER/32), blk, 0, cx.s2>>>(Wk, wkvth, wkvtl, CD, INNER);
    wtrans_kernel<<<dim3(CD/32, INNER/32), blk, 0, cx.s2>>>(
        Wv, wkvth + (size_t)INNER*CD, wkvtl + (size_t)INNER*CD, CD, INNER);
    wtrans_kernel<<<dim3(INNER/32, QD/32), blk, 0, cx.s2>>>(Wo, woth, wotl, INNER, QD);
    gemm_bf16x3<<<dim3(KVN/G_BN, MKV/G_BM), 256, G_SMEM, cx.s2>>>(
        ctxp, nullptr, nullptr, wkvth, wkvtl, nullptr, kv, nullptr, nullptr,
        BB*CTX, KVN, CD);
    kv_image_kernel<<<NBH, 128, 0, cx.s2>>>();
    cudaEventRecord(cx.evSide, cx.s2);

    // main chain: Wq transpose, then full-size Q GEMM (1280 CTAs, best waves)
    wtrans_kernel<<<dim3(QD/32, INNER/32), blk>>>(Wq, wqth, wqtl, QD, INNER);
    gemm_bf16x3<<<dim3(INNER/G_BN, (BB*NQ)/G_BM), 256, G_SMEM>>>(
        x, nullptr, nullptr, wqth, wqtl, nullptr, nullptr, qhi, qlo,
        BB*NQ, INNER, QD);
    cudaEventRecord(cx.evQ, 0);

    // attention halves on s3 (both strictly after full Q + side chain)
    cudaStreamWaitEvent(cx.s3, cx.evQ, 0);
    cudaStreamWaitEvent(cx.s3, cx.evSide, 0);
    attn_tc<<<attn_half_grid, 128, ATTN_SMEM, cx.s3>>>(0);
    cudaEventRecord(cx.evA0, cx.s3);
    attn_tc<<<attn_half_grid, 128, ATTN_SMEM, cx.s3>>>(BB/2);
    cudaEventRecord(cx.evA1, cx.s3);

    // O-GEMM halves: O0 runs concurrent with attn1 (the only overlap window)
    cudaStreamWaitEvent(0, cx.evA0, 0);
    gemm_bf16x3<<<ogemm_half_grid, 256, G_SMEM>>>(
        nullptr, aohi, aolo, woth, wotl, bo, out, nullptr, nullptr,
        MHALF, QD, INNER);
    cudaStreamWaitEvent(0, cx.evA1, 0);
    gemm_bf16x3<<<ogemm_half_grid, 256, G_SMEM>>>(
        nullptr, aohi + (size_t)MHALF*INNER, aolo + (size_t)MHALF*INNER,
        woth, wotl, bo, out + (size_t)MHALF*QD, nullptr, nullptr,
        MHALF, QD, INNER);
}